// round 15
// baseline (speedup 1.0000x reference)
#include <cuda_runtime.h>
#include <math.h>

#define NN 50000
#define EE 800000
#define CC 32
#define ZZ 10
#define LL 2
#define NB 8
#define HH 64
#define TT 8192
#define INV_AVG (1.0f/16.0f)
#define RCUT_INV (1.0f/5.0f)

// ---------------- scratch (static device globals; no allocation) -------------
__device__ float4 g_sv [NN*CC];   // {s, v0, v1, v2}
__device__ float4 g_up [NN*CC];   // {su, vu0, vu1, vu2}
__device__ float4 g_acc[NN*CC];   // {S, V0, V1, V2}
__device__ float4 g_Y1 [EE];      // unsorted edge geometry
__device__ float  g_tc [EE];      // table coordinate (r mapped to [0, TT-1])
__device__ int2   g_edge [EE];    // {src, dst}
__device__ int    g_z  [NN];
__device__ float  g_su0[ZZ*CC];   // layer-0 su table (species-only)
__device__ float  g_wtab[LL*TT*5*CC];  // radial-MLP output table per layer
// sorted/compacted active-edge arrays (counting sort by table bin)
__device__ int    g_bcnt[TT];
__device__ int    g_pos [TT];
__device__ int    g_M;            // number of active edges (r < rcut)
__device__ float4 g_Y1s [EE];
__device__ float  g_tcs [EE];
__device__ int2   g_edges[EE];

__device__ __forceinline__ float silu(float x) {
    return __fdividef(x, 1.0f + __expf(-x));
}
__device__ __forceinline__ void red_v4(float4* p, float a, float b, float c, float d) {
    asm volatile("red.global.add.v4.f32 [%0], {%1,%2,%3,%4};"
                 :: "l"(p), "f"(a), "f"(b), "f"(c), "f"(d) : "memory");
}

// ---------------- layer-0 su table: su0[z] = W_embed[z] @ W_up_s[0] ----------
// also zeroes the histogram bins (runs first)
__global__ void k_pre0(const float* __restrict__ W_embed,
                       const float* __restrict__ Wus) {
    int t = blockIdx.x * blockDim.x + threadIdx.x;
    if (t < TT) g_bcnt[t] = 0;
    if (t >= ZZ*32) return;
    int z = t >> 5, lane = t & 31;
    float a = 0.f;
#pragma unroll
    for (int k = 0; k < CC; k++)
        a += W_embed[z*CC + k] * Wus[k*CC + lane];
    g_su0[z*CC + lane] = a;
}

// ---------------- fused init: species (ballot), s=embed, v=0, up, acc=0 ------
__global__ void k_init0(const float* __restrict__ attrs,
                        const float* __restrict__ W_embed) {
    int idx = blockIdx.x * blockDim.x + threadIdx.x;
    if (idx >= NN*CC) return;
    int n = idx >> 5, lane = idx & 31;
    float av = (lane < ZZ) ? __ldg(attrs + n*ZZ + lane) : 0.f;
    unsigned m = __ballot_sync(0xffffffffu, av > 0.5f);
    int z = m ? (__ffs(m) - 1) : 0;
    if (lane == 0) g_z[n] = z;
    g_sv [idx] = make_float4(__ldg(W_embed + z*CC + lane), 0.f, 0.f, 0.f);
    g_up [idx] = make_float4(g_su0[z*CC + lane],           0.f, 0.f, 0.f);
    g_acc[idx] = make_float4(0.f, 0.f, 0.f, 0.f);
}

// ---------------- edge geometry: Y1 + table coord + histogram ----------------
// Edges with r >= rcut have fc=0 -> w=0 -> EXACT zero message (reference too);
// excluded from the histogram and never processed again.
__global__ void k_geom(const float* __restrict__ pos,
                       const float* __restrict__ shifts,
                       const int* __restrict__ src,
                       const int* __restrict__ dst) {
    int e = blockIdx.x * blockDim.x + threadIdx.x;
    if (e >= EE) return;
    int si = src[e], di = dst[e];
    g_edge[e] = make_int2(si, di);
    float vx = pos[di*3+0] - pos[si*3+0] + shifts[e*3+0];
    float vy = pos[di*3+1] - pos[si*3+1] + shifts[e*3+1];
    float vz = pos[di*3+2] - pos[si*3+2] + shifts[e*3+2];
    float r  = sqrtf(vx*vx + vy*vy + vz*vz);
    float rs = fmaxf(r, 1e-9f);
    float inv = 1.0f / rs;
    g_Y1[e] = make_float4(vx*inv, vy*inv, vz*inv, 0.f);
    float x = r * RCUT_INV;
    float tc = fminf(x, 1.0f) * (float)(TT - 1);
    g_tc[e] = tc;
    if (tc < (float)(TT - 1))
        atomicAdd(&g_bcnt[min((int)tc, TT - 2)], 1);
}

// ---------------- exclusive scan over 8192 bins (one block) ------------------
__global__ void k_scan() {
    __shared__ int s[1024];
    int t = threadIdx.x;
    int c[8], sum = 0;
#pragma unroll
    for (int j = 0; j < 8; j++) { c[j] = g_bcnt[t*8 + j]; sum += c[j]; }
    s[t] = sum;
    __syncthreads();
    for (int off = 1; off < 1024; off <<= 1) {
        int v = (t >= off) ? s[t - off] : 0;
        __syncthreads();
        s[t] += v;
        __syncthreads();
    }
    int run = (t == 0) ? 0 : s[t - 1];
#pragma unroll
    for (int j = 0; j < 8; j++) { g_pos[t*8 + j] = run; run += c[j]; }
    if (t == 1023) g_M = s[1023];
}

// ---------------- radial-MLP table build (both layers, one launch) -----------
__global__ void k_table(const float* __restrict__ R1,
                        const float* __restrict__ R2,
                        const float* __restrict__ R3) {
    int layer = blockIdx.x >= (TT/8) ? 1 : 0;
    int bi = blockIdx.x - layer*(TT/8);
    const float* R1l = R1 + layer*NB*HH;
    const float* R2l = R2 + layer*HH*HH;
    const float* R3l = R3 + layer*HH*5*CC;
    extern __shared__ float sm[];
    float* sR1 = sm;                 // 8*64
    float* sR2 = sR1 + NB*HH;        // 64*64
    float* sR3 = sR2 + HH*HH;        // 64*160
    int tid = threadIdx.x;
    for (int i = tid; i < NB*HH;   i += blockDim.x) sR1[i] = R1l[i];
    for (int i = tid; i < HH*HH;   i += blockDim.x) sR2[i] = R2l[i];
    for (int i = tid; i < HH*5*CC; i += blockDim.x) sR3[i] = R3l[i];
    __syncthreads();

    int warp = tid >> 5, lane = tid & 31;
    int i = bi * (blockDim.x >> 5) + warp;
    if (i >= TT) return;

    float r  = 5.0f * (float)i / (float)(TT - 1);
    float rs = fmaxf(r, 1e-9f);
    float inv = 1.0f / rs;
    float x = r * RCUT_INV;
    float fc = 0.f;
    if (x < 1.0f) {
        float x2 = x*x, x3 = x2*x;
        float x6 = x3*x3, x7 = x6*x, x8 = x7*x;
        fc = 1.0f - 28.0f*x6 + 48.0f*x7 - 21.0f*x8;
    }
    float coef = 0.6324555320336759f * fc * inv;
    float arg0 = rs * (float)M_PI * RCUT_INV;
    float ef[NB];
#pragma unroll
    for (int nb = 0; nb < NB; nb++)
        ef[nb] = coef * sinf((float)(nb+1) * arg0);

    float h0 = 0.f, h1 = 0.f;
#pragma unroll
    for (int k = 0; k < NB; k++) {
        h0 += ef[k] * sR1[k*HH + lane];
        h1 += ef[k] * sR1[k*HH + lane + 32];
    }
    h0 = silu(h0); h1 = silu(h1);

    float a0 = 0.f, a1 = 0.f;
#pragma unroll
    for (int k = 0; k < 32; k++) {
        float va = __shfl_sync(0xffffffffu, h0, k);
        float vb = __shfl_sync(0xffffffffu, h1, k);
        a0 += va * sR2[k*HH + lane]        + vb * sR2[(k+32)*HH + lane];
        a1 += va * sR2[k*HH + lane + 32]   + vb * sR2[(k+32)*HH + lane + 32];
    }
    a0 = silu(a0); a1 = silu(a1);

    float w[5] = {0.f, 0.f, 0.f, 0.f, 0.f};
#pragma unroll
    for (int k = 0; k < 32; k++) {
        float va = __shfl_sync(0xffffffffu, a0, k);
        float vb = __shfl_sync(0xffffffffu, a1, k);
#pragma unroll
        for (int p = 0; p < 5; p++)
            w[p] += va * sR3[k*5*CC + p*CC + lane]
                  + vb * sR3[(k+32)*5*CC + p*CC + lane];
    }
    float* out = g_wtab + ((size_t)layer*TT + i) * (5*CC);
#pragma unroll
    for (int p = 0; p < 5; p++)
        out[p*CC + lane] = w[p];
}

// ---------------- fused scatter + LAYER-0 edge message ------------------------
// Warp per edge. Active edges: compact into bin-sorted arrays AND compute the
// layer-0 TP message (v==0 → only paths 0,1; ss from species table) directly
// from registers — no separate L0 edge kernel, no re-read of sorted arrays.
__global__ void __launch_bounds__(256)
k_scatter() {
    __shared__ float sSU0[ZZ*CC];
    for (int i = threadIdx.x; i < ZZ*CC; i += blockDim.x) sSU0[i] = g_su0[i];
    __syncthreads();
    int gw = (blockIdx.x * blockDim.x + threadIdx.x) >> 5;
    if (gw >= EE) return;
    int lane = threadIdx.x & 31;

    float tc = __ldg(g_tc + gw);
    if (tc >= (float)(TT - 1)) return;        // zero-message edge: drop
    int bin = min((int)tc, TT - 2);
    int pos = 0;
    if (lane == 0) pos = atomicAdd(&g_pos[bin], 1);
    pos = __shfl_sync(0xffffffffu, pos, 0);

    int2   sd = __ldg(g_edge + gw);
    float4 y4 = __ldg(g_Y1 + gw);
    if (lane == 0) { g_tcs[pos] = tc; g_edges[pos] = sd; }
    if (lane == 1) g_Y1s[pos] = y4;

    // layer-0 message: lane = channel
    int z = __ldg(g_z + sd.x);
    float f = tc - (float)bin;
    const float* rowA = g_wtab + (size_t)bin * (5*CC);
    float a0 = __ldg(rowA + lane),      b0 = __ldg(rowA + 5*CC + lane);
    float a1 = __ldg(rowA + CC + lane), b1 = __ldg(rowA + 5*CC + CC + lane);
    float w0 = fmaf(f, b0 - a0, a0);
    float w1 = fmaf(f, b1 - a1, a1);
    float ss = sSU0[z*CC + lane];
    float ms  = w0 * ss;
    float w1s = w1 * ss;
    red_v4(g_acc + sd.y*CC + lane, ms, w1s*y4.x, w1s*y4.y, w1s*y4.z);
}

// ---------------- layer-1 edge kernel: sorted, table interp + scatter --------
#define EBLK 1184
__global__ void __launch_bounds__(256)
k_edge2() {
    int M = g_M;
    int chunk = (M + EBLK - 1) / EBLK;
    int start = blockIdx.x * chunk;
    int end   = min(start + chunk, M);
    int wib = threadIdx.x >> 5, lane = threadIdx.x & 31;
    const float* tab = g_wtab + (size_t)TT*(5*CC);   // layer 1

    for (int e = start + wib; e < end; e += 8) {
        int2 sd = __ldg(g_edges + e);
        float tc = __ldg(g_tcs + e);
        int i0 = min((int)tc, TT - 2);
        float f = tc - (float)i0;
        const float* rowA = tab + (size_t)i0 * (5*CC);
        float w[5];
#pragma unroll
        for (int p = 0; p < 5; p++) {
            float a = __ldg(rowA + p*CC + lane);
            float b = __ldg(rowA + 5*CC + p*CC + lane);
            w[p] = fmaf(f, b - a, a);
        }
        float4 y4 = __ldg(g_Y1s + e);
        float y0 = y4.x, y1 = y4.y, y2 = y4.z;
        float4 uv = __ldg(g_up + sd.x*CC + lane);
        float ss = uv.x, v0 = uv.y, v1 = uv.z, v2 = uv.w;
        float dot = v0*y0 + v1*y1 + v2*y2;
        float c0 = v1*y2 - v2*y1;
        float c1 = v2*y0 - v0*y2;
        float c2 = v0*y1 - v1*y0;
        float ms = w[0]*ss + w[3]*dot;
        float m0 = w[1]*ss*y0 + w[2]*v0 + w[4]*c0;
        float m1 = w[1]*ss*y1 + w[2]*v1 + w[4]*c1;
        float m2 = w[1]*ss*y2 + w[2]*v2 + w[4]*c2;
        red_v4(g_acc + sd.y*CC + lane, ms, m0, m1, m2);
    }
}

// ---------------- node update: out linears, skip, product block --------------
#define NWB 16
template<bool FUSE>
__global__ void k_nodeupd(const float* __restrict__ Wouts,
                          const float* __restrict__ Woutv,
                          const float* __restrict__ Wscs,
                          const float* __restrict__ Wscv,
                          const float* __restrict__ Wp,
                          const float* __restrict__ Wlins,
                          const float* __restrict__ Wlinv,
                          const float* __restrict__ WusN,
                          const float* __restrict__ WuvN,
                          float* __restrict__ out, int l) {
    __shared__ float sWos[CC*CC], sWov[CC*CC], sWls[CC*CC], sWlv[CC*CC];
    __shared__ float sWus[CC*CC], sWuv[CC*CC];
    __shared__ float st[NWB][256];
    int tid = threadIdx.x;
    for (int i = tid; i < CC*CC; i += blockDim.x) {
        sWos[i] = Wouts[i]; sWov[i] = Woutv[i];
        sWls[i] = Wlins[i]; sWlv[i] = Wlinv[i];
        if (FUSE) { sWus[i] = WusN[i]; sWuv[i] = WuvN[i]; }
    }
    __syncthreads();
    int warp = tid >> 5, lane = tid & 31;
    int n = blockIdx.x * NWB + warp;
    if (n >= NN) return;

    float* xs = st[warp];
    float* xv = xs + 32;
    float* ys = xv + 96;
    float* yv = ys + 32;

    int z = g_z[n];
    float4 a4 = g_acc[n*CC + lane];
    float4 o4 = g_sv [n*CC + lane];
    xs[lane]       = a4.x * INV_AVG;
    xv[lane*3 + 0] = a4.y * INV_AVG;
    xv[lane*3 + 1] = a4.z * INV_AVG;
    xv[lane*3 + 2] = a4.w * INV_AVG;
    ys[lane]       = o4.x;
    yv[lane*3 + 0] = o4.y;
    yv[lane*3 + 1] = o4.z;
    yv[lane*3 + 2] = o4.w;
    __syncwarp();

    const float* Ws = Wscs + z*CC*CC;
    const float* Wv = Wscv + z*CC*CC;
    float s2 = 0.f, v20 = 0.f, v21 = 0.f, v22 = 0.f;
    float scs = 0.f, sv0 = 0.f, sv1 = 0.f, sv2 = 0.f;
#pragma unroll
    for (int k = 0; k < CC; k++) {
        float wo = sWos[k*CC + lane], wvv = sWov[k*CC + lane];
        s2  += xs[k]     * wo;
        v20 += xv[k*3+0] * wvv;
        v21 += xv[k*3+1] * wvv;
        v22 += xv[k*3+2] * wvv;
        float as = __ldg(Ws + k*CC + lane), av = __ldg(Wv + k*CC + lane);
        scs += ys[k]     * as;
        sv0 += yv[k*3+0] * av;
        sv1 += yv[k*3+1] * av;
        sv2 += yv[k*3+2] * av;
    }

    float we0 = __ldg(Wp + (z*5+0)*CC + lane);
    float we1 = __ldg(Wp + (z*5+1)*CC + lane);
    float we2 = __ldg(Wp + (z*5+2)*CC + lane);
    float we3 = __ldg(Wp + (z*5+3)*CC + lane);
    float we4 = __ldg(Wp + (z*5+4)*CC + lane);

    float vdot = v20*v20 + v21*v21 + v22*v22;
    float ps  = we0*s2 + we1*s2*s2 + we2*vdot;
    float pv0 = we3*v20 + we4*s2*v20;
    float pv1 = we3*v21 + we4*s2*v21;
    float pv2 = we3*v22 + we4*s2*v22;
    __syncwarp();
    xs[lane] = ps;
    xv[lane*3+0] = pv0; xv[lane*3+1] = pv1; xv[lane*3+2] = pv2;
    __syncwarp();

    float sn = scs, vn0 = sv0, vn1 = sv1, vn2 = sv2;
#pragma unroll
    for (int k = 0; k < CC; k++) {
        float wl = sWls[k*CC + lane], wlv = sWlv[k*CC + lane];
        sn  += xs[k]     * wl;
        vn0 += xv[k*3+0] * wlv;
        vn1 += xv[k*3+1] * wlv;
        vn2 += xv[k*3+2] * wlv;
    }
    g_sv[n*CC + lane] = make_float4(sn, vn0, vn1, vn2);
    out[n*(LL*CC) + l*CC + lane] = sn;

    if (FUSE) {
        __syncwarp();
        ys[lane]       = sn;
        yv[lane*3 + 0] = vn0;
        yv[lane*3 + 1] = vn1;
        yv[lane*3 + 2] = vn2;
        __syncwarp();
        float a = 0.f, u0 = 0.f, u1 = 0.f, u2 = 0.f;
#pragma unroll
        for (int k = 0; k < CC; k++) {
            float ws = sWus[k*CC + lane], wv = sWuv[k*CC + lane];
            a  += ys[k]     * ws;
            u0 += yv[k*3+0] * wv;
            u1 += yv[k*3+1] * wv;
            u2 += yv[k*3+2] * wv;
        }
        g_up [n*CC + lane] = make_float4(a, u0, u1, u2);
        g_acc[n*CC + lane] = make_float4(0.f, 0.f, 0.f, 0.f);
    }
}

// ---------------- launch ------------------------------------------------------
extern "C" void kernel_launch(void* const* d_in, const int* in_sizes, int n_in,
                              void* d_out, int out_size) {
    const float* pos     = (const float*)d_in[0];
    const float* attrs   = (const float*)d_in[1];
    const float* shifts  = (const float*)d_in[2];
    const float* W_embed = (const float*)d_in[3];
    const float* W_up_s  = (const float*)d_in[4];
    const float* W_up_v  = (const float*)d_in[5];
    const float* R1      = (const float*)d_in[6];
    const float* R2      = (const float*)d_in[7];
    const float* R3      = (const float*)d_in[8];
    const float* W_out_s = (const float*)d_in[9];
    const float* W_out_v = (const float*)d_in[10];
    const float* Wsc_s   = (const float*)d_in[11];
    const float* Wsc_v   = (const float*)d_in[12];
    const float* Wp      = (const float*)d_in[13];
    const float* W_lin_s = (const float*)d_in[14];
    const float* W_lin_v = (const float*)d_in[15];
    const int*   ei      = (const int*)d_in[16];
    const int* src = ei;
    const int* dst = ei + EE;
    float* out = (float*)d_out;

    int smemT = (NB*HH + HH*HH + HH*5*CC) * (int)sizeof(float);   // 59392 B
    cudaFuncSetAttribute(k_table, cudaFuncAttributeMaxDynamicSharedMemorySize, smemT);

    k_pre0 <<<(TT + 255)/256, 256>>>(W_embed, W_up_s);           // su0 + zero bins
    k_init0<<<(NN*CC + 255)/256, 256>>>(attrs, W_embed);         // z + s/v/up/acc
    k_geom <<<(EE + 255)/256, 256>>>(pos, shifts, src, dst);     // Y1/tc/hist
    k_table<<<2*(TT/8), 256, smemT>>>(R1, R2, R3);               // both layers
    k_scan <<<1, 1024>>>();
    k_scatter<<<(EE*32 + 255)/256, 256>>>();                     // compact + L0 msgs

    // layer-0 node update (fuses layer-1 up-projection + acc zeroing)
    k_nodeupd<true><<<(NN + NWB - 1)/NWB, NWB*32>>>(
        W_out_s, W_out_v, Wsc_s, Wsc_v, Wp, W_lin_s, W_lin_v,
        W_up_s + CC*CC, W_up_v + CC*CC, out, 0);

    // layer 1
    k_edge2<<<EBLK, 256>>>();
    k_nodeupd<false><<<(NN + NWB - 1)/NWB, NWB*32>>>(
        W_out_s + CC*CC, W_out_v + CC*CC,
        Wsc_s + ZZ*CC*CC, Wsc_v + ZZ*CC*CC, Wp + ZZ*5*CC,
        W_lin_s + CC*CC, W_lin_v + CC*CC,
        W_up_s, W_up_v, out, 1);
}

// round 16
// speedup vs baseline: 1.2383x; 1.2383x over previous
#include <cuda_runtime.h>
#include <math.h>

#define NN 50000
#define EE 800000
#define CC 32
#define ZZ 10
#define LL 2
#define NB 8
#define HH 64
#define TT 4096
#define INV_AVG (1.0f/16.0f)
#define RCUT_INV (1.0f/5.0f)

// ---------------- scratch (static device globals; no allocation) -------------
__device__ float4 g_sv [NN*CC];   // {s, v0, v1, v2}
__device__ float4 g_up [NN*CC];   // {su, vu0, vu1, vu2}
__device__ float4 g_acc[NN*CC];   // {S, V0, V1, V2}
__device__ float4 g_Y1 [EE];      // unsorted edge geometry
__device__ float  g_tc [EE];      // table coordinate (r mapped to [0, TT-1])
__device__ int2   g_edge [EE];    // {src, dst}
__device__ int    g_z  [NN];
__device__ float  g_su0[ZZ*CC];   // layer-0 su table (species-only)
__device__ float  g_wtab[LL*TT*5*CC];  // radial-MLP output table per layer
// sorted/compacted active-edge arrays (counting sort by table bin)
__device__ int    g_bcnt[TT];
__device__ int    g_pos [TT];
__device__ int    g_M;            // number of active edges (r < rcut)
__device__ float4 g_Y1s [EE];
__device__ float  g_tcs [EE];
__device__ int2   g_edges[EE];

__device__ __forceinline__ float silu(float x) {
    return __fdividef(x, 1.0f + __expf(-x));
}
__device__ __forceinline__ void red_v4(float4* p, float a, float b, float c, float d) {
    asm volatile("red.global.add.v4.f32 [%0], {%1,%2,%3,%4};"
                 :: "l"(p), "f"(a), "f"(b), "f"(c), "f"(d) : "memory");
}

// ---------------- layer-0 su table + zero histogram bins ---------------------
__global__ void k_pre0(const float* __restrict__ W_embed,
                       const float* __restrict__ Wus) {
    int t = blockIdx.x * blockDim.x + threadIdx.x;
    if (t < TT) g_bcnt[t] = 0;
    if (t >= ZZ*32) return;
    int z = t >> 5, lane = t & 31;
    float a = 0.f;
#pragma unroll
    for (int k = 0; k < CC; k++)
        a += W_embed[z*CC + k] * Wus[k*CC + lane];
    g_su0[z*CC + lane] = a;
}

// ---------------- fused init: species (ballot), s=embed, v=0, up, acc=0 ------
__global__ void k_init0(const float* __restrict__ attrs,
                        const float* __restrict__ W_embed) {
    int idx = blockIdx.x * blockDim.x + threadIdx.x;
    if (idx >= NN*CC) return;
    int n = idx >> 5, lane = idx & 31;
    float av = (lane < ZZ) ? __ldg(attrs + n*ZZ + lane) : 0.f;
    unsigned m = __ballot_sync(0xffffffffu, av > 0.5f);
    int z = m ? (__ffs(m) - 1) : 0;
    if (lane == 0) g_z[n] = z;
    g_sv [idx] = make_float4(__ldg(W_embed + z*CC + lane), 0.f, 0.f, 0.f);
    g_up [idx] = make_float4(g_su0[z*CC + lane],           0.f, 0.f, 0.f);
    g_acc[idx] = make_float4(0.f, 0.f, 0.f, 0.f);
}

// ---------------- edge geometry: Y1 + table coord + histogram ----------------
// Edges with r >= rcut have fc=0 -> w=0 -> EXACT zero message (reference too);
// excluded from the histogram and never processed again.
__global__ void k_geom(const float* __restrict__ pos,
                       const float* __restrict__ shifts,
                       const int* __restrict__ src,
                       const int* __restrict__ dst) {
    int e = blockIdx.x * blockDim.x + threadIdx.x;
    if (e >= EE) return;
    int si = src[e], di = dst[e];
    g_edge[e] = make_int2(si, di);
    float vx = pos[di*3+0] - pos[si*3+0] + shifts[e*3+0];
    float vy = pos[di*3+1] - pos[si*3+1] + shifts[e*3+1];
    float vz = pos[di*3+2] - pos[si*3+2] + shifts[e*3+2];
    float r  = sqrtf(vx*vx + vy*vy + vz*vz);
    float rs = fmaxf(r, 1e-9f);
    float inv = 1.0f / rs;
    g_Y1[e] = make_float4(vx*inv, vy*inv, vz*inv, 0.f);
    float x = r * RCUT_INV;
    float tc = fminf(x, 1.0f) * (float)(TT - 1);
    g_tc[e] = tc;
    if (tc < (float)(TT - 1))
        atomicAdd(&g_bcnt[min((int)tc, TT - 2)], 1);
}

// ---------------- exclusive scan over TT bins (one block) --------------------
__global__ void k_scan() {
    __shared__ int s[1024];
    const int J = TT / 1024;
    int t = threadIdx.x;
    int c[J], sum = 0;
#pragma unroll
    for (int j = 0; j < J; j++) { c[j] = g_bcnt[t*J + j]; sum += c[j]; }
    s[t] = sum;
    __syncthreads();
    for (int off = 1; off < 1024; off <<= 1) {
        int v = (t >= off) ? s[t - off] : 0;
        __syncthreads();
        s[t] += v;
        __syncthreads();
    }
    int run = (t == 0) ? 0 : s[t - 1];
#pragma unroll
    for (int j = 0; j < J; j++) { g_pos[t*J + j] = run; run += c[j]; }
    if (t == 1023) g_M = s[1023];
}

// ---------------- scatter active edges into bin-sorted order ------------------
__global__ void k_scatter() {
    int e = blockIdx.x * blockDim.x + threadIdx.x;
    if (e >= EE) return;
    float tc = g_tc[e];
    if (tc >= (float)(TT - 1)) return;        // zero-message edge: drop
    int bin = min((int)tc, TT - 2);
    int pos = atomicAdd(&g_pos[bin], 1);
    g_tcs  [pos] = tc;
    g_Y1s  [pos] = g_Y1[e];
    g_edges[pos] = g_edge[e];
}

// ---------------- radial-MLP table build (both layers, one launch) -----------
__global__ void k_table(const float* __restrict__ R1,
                        const float* __restrict__ R2,
                        const float* __restrict__ R3) {
    int layer = blockIdx.x >= (TT/8) ? 1 : 0;
    int bi = blockIdx.x - layer*(TT/8);
    const float* R1l = R1 + layer*NB*HH;
    const float* R2l = R2 + layer*HH*HH;
    const float* R3l = R3 + layer*HH*5*CC;
    extern __shared__ float sm[];
    float* sR1 = sm;                 // 8*64
    float* sR2 = sR1 + NB*HH;        // 64*64
    float* sR3 = sR2 + HH*HH;        // 64*160
    int tid = threadIdx.x;
    for (int i = tid; i < NB*HH;   i += blockDim.x) sR1[i] = R1l[i];
    for (int i = tid; i < HH*HH;   i += blockDim.x) sR2[i] = R2l[i];
    for (int i = tid; i < HH*5*CC; i += blockDim.x) sR3[i] = R3l[i];
    __syncthreads();

    int warp = tid >> 5, lane = tid & 31;
    int i = bi * (blockDim.x >> 5) + warp;
    if (i >= TT) return;

    float r  = 5.0f * (float)i / (float)(TT - 1);
    float rs = fmaxf(r, 1e-9f);
    float inv = 1.0f / rs;
    float x = r * RCUT_INV;
    float fc = 0.f;
    if (x < 1.0f) {
        float x2 = x*x, x3 = x2*x;
        float x6 = x3*x3, x7 = x6*x, x8 = x7*x;
        fc = 1.0f - 28.0f*x6 + 48.0f*x7 - 21.0f*x8;
    }
    float coef = 0.6324555320336759f * fc * inv;
    float arg0 = rs * (float)M_PI * RCUT_INV;
    float ef[NB];
#pragma unroll
    for (int nb = 0; nb < NB; nb++)
        ef[nb] = coef * sinf((float)(nb+1) * arg0);

    float h0 = 0.f, h1 = 0.f;
#pragma unroll
    for (int k = 0; k < NB; k++) {
        h0 += ef[k] * sR1[k*HH + lane];
        h1 += ef[k] * sR1[k*HH + lane + 32];
    }
    h0 = silu(h0); h1 = silu(h1);

    float a0 = 0.f, a1 = 0.f;
#pragma unroll
    for (int k = 0; k < 32; k++) {
        float va = __shfl_sync(0xffffffffu, h0, k);
        float vb = __shfl_sync(0xffffffffu, h1, k);
        a0 += va * sR2[k*HH + lane]        + vb * sR2[(k+32)*HH + lane];
        a1 += va * sR2[k*HH + lane + 32]   + vb * sR2[(k+32)*HH + lane + 32];
    }
    a0 = silu(a0); a1 = silu(a1);

    float w[5] = {0.f, 0.f, 0.f, 0.f, 0.f};
#pragma unroll
    for (int k = 0; k < 32; k++) {
        float va = __shfl_sync(0xffffffffu, a0, k);
        float vb = __shfl_sync(0xffffffffu, a1, k);
#pragma unroll
        for (int p = 0; p < 5; p++)
            w[p] += va * sR3[k*5*CC + p*CC + lane]
                  + vb * sR3[(k+32)*5*CC + p*CC + lane];
    }
    float* out = g_wtab + ((size_t)layer*TT + i) * (5*CC);
#pragma unroll
    for (int p = 0; p < 5; p++)
        out[p*CC + lane] = w[p];
}

// ---------------- edge kernel: sorted active edges, table interp + scatter ---
// Block owns a CONTIGUOUS chunk of bin-sorted edges -> neighboring edges share
// table rows -> table reads are L1 hits. Warp per edge; lane = channel.
#define EBLK 1184
template<int NP>
__global__ void __launch_bounds__(256)
k_edge2(int layer) {
    __shared__ float sSU0[ZZ*CC];
    if (NP == 2) {
        for (int i = threadIdx.x; i < ZZ*CC; i += blockDim.x) sSU0[i] = g_su0[i];
        __syncthreads();
    }
    int M = g_M;
    int chunk = (M + EBLK - 1) / EBLK;
    int start = blockIdx.x * chunk;
    int end   = min(start + chunk, M);
    int wib = threadIdx.x >> 5, lane = threadIdx.x & 31;
    const float* tab = g_wtab + (size_t)layer*TT*(5*CC);
    constexpr int NW = (NP == 2) ? 2 : 5;

    for (int e = start + wib; e < end; e += 8) {
        int2 sd = __ldg(g_edges + e);
        float tc = __ldg(g_tcs + e);
        int i0 = min((int)tc, TT - 2);
        float f = tc - (float)i0;
        const float* rowA = tab + (size_t)i0 * (5*CC);
        float w[NW];
#pragma unroll
        for (int p = 0; p < NW; p++) {
            float a = __ldg(rowA + p*CC + lane);
            float b = __ldg(rowA + 5*CC + p*CC + lane);
            w[p] = fmaf(f, b - a, a);
        }
        float4 y4 = __ldg(g_Y1s + e);
        float y0 = y4.x, y1 = y4.y, y2 = y4.z;
        float ms, m0, m1, m2;
        if (NP == 2) {
            int z = __ldg(g_z + sd.x);             // broadcast, cache-resident
            float ss = sSU0[z*CC + lane];
            ms = w[0] * ss;
            float w1s = w[1] * ss;
            m0 = w1s*y0; m1 = w1s*y1; m2 = w1s*y2;
        } else {
            float4 uv = __ldg(g_up + sd.x*CC + lane);
            float ss = uv.x, v0 = uv.y, v1 = uv.z, v2 = uv.w;
            float dot = v0*y0 + v1*y1 + v2*y2;
            float c0 = v1*y2 - v2*y1;
            float c1 = v2*y0 - v0*y2;
            float c2 = v0*y1 - v1*y0;
            ms = w[0]*ss + w[3]*dot;
            m0 = w[1]*ss*y0 + w[2]*v0 + w[4]*c0;
            m1 = w[1]*ss*y1 + w[2]*v1 + w[4]*c1;
            m2 = w[1]*ss*y2 + w[2]*v2 + w[4]*c2;
        }
        red_v4(g_acc + sd.y*CC + lane, ms, m0, m1, m2);
    }
}

// ---------------- node update: out linears, skip, product block --------------
#define NWB 16
template<bool FUSE>
__global__ void k_nodeupd(const float* __restrict__ Wouts,
                          const float* __restrict__ Woutv,
                          const float* __restrict__ Wscs,
                          const float* __restrict__ Wscv,
                          const float* __restrict__ Wp,
                          const float* __restrict__ Wlins,
                          const float* __restrict__ Wlinv,
                          const float* __restrict__ WusN,
                          const float* __restrict__ WuvN,
                          float* __restrict__ out, int l) {
    __shared__ float sWos[CC*CC], sWov[CC*CC], sWls[CC*CC], sWlv[CC*CC];
    __shared__ float sWus[CC*CC], sWuv[CC*CC];
    __shared__ float st[NWB][256];
    int tid = threadIdx.x;
    for (int i = tid; i < CC*CC; i += blockDim.x) {
        sWos[i] = Wouts[i]; sWov[i] = Woutv[i];
        sWls[i] = Wlins[i]; sWlv[i] = Wlinv[i];
        if (FUSE) { sWus[i] = WusN[i]; sWuv[i] = WuvN[i]; }
    }
    __syncthreads();
    int warp = tid >> 5, lane = tid & 31;
    int n = blockIdx.x * NWB + warp;
    if (n >= NN) return;

    float* xs = st[warp];
    float* xv = xs + 32;
    float* ys = xv + 96;
    float* yv = ys + 32;

    int z = g_z[n];
    float4 a4 = g_acc[n*CC + lane];
    float4 o4 = g_sv [n*CC + lane];
    xs[lane]       = a4.x * INV_AVG;
    xv[lane*3 + 0] = a4.y * INV_AVG;
    xv[lane*3 + 1] = a4.z * INV_AVG;
    xv[lane*3 + 2] = a4.w * INV_AVG;
    ys[lane]       = o4.x;
    yv[lane*3 + 0] = o4.y;
    yv[lane*3 + 1] = o4.z;
    yv[lane*3 + 2] = o4.w;
    __syncwarp();

    const float* Ws = Wscs + z*CC*CC;
    const float* Wv = Wscv + z*CC*CC;
    float s2 = 0.f, v20 = 0.f, v21 = 0.f, v22 = 0.f;
    float scs = 0.f, sv0 = 0.f, sv1 = 0.f, sv2 = 0.f;
#pragma unroll
    for (int k = 0; k < CC; k++) {
        float wo = sWos[k*CC + lane], wvv = sWov[k*CC + lane];
        s2  += xs[k]     * wo;
        v20 += xv[k*3+0] * wvv;
        v21 += xv[k*3+1] * wvv;
        v22 += xv[k*3+2] * wvv;
        float as = __ldg(Ws + k*CC + lane), av = __ldg(Wv + k*CC + lane);
        scs += ys[k]     * as;
        sv0 += yv[k*3+0] * av;
        sv1 += yv[k*3+1] * av;
        sv2 += yv[k*3+2] * av;
    }

    float we0 = __ldg(Wp + (z*5+0)*CC + lane);
    float we1 = __ldg(Wp + (z*5+1)*CC + lane);
    float we2 = __ldg(Wp + (z*5+2)*CC + lane);
    float we3 = __ldg(Wp + (z*5+3)*CC + lane);
    float we4 = __ldg(Wp + (z*5+4)*CC + lane);

    float vdot = v20*v20 + v21*v21 + v22*v22;
    float ps  = we0*s2 + we1*s2*s2 + we2*vdot;
    float pv0 = we3*v20 + we4*s2*v20;
    float pv1 = we3*v21 + we4*s2*v21;
    float pv2 = we3*v22 + we4*s2*v22;
    __syncwarp();
    xs[lane] = ps;
    xv[lane*3+0] = pv0; xv[lane*3+1] = pv1; xv[lane*3+2] = pv2;
    __syncwarp();

    float sn = scs, vn0 = sv0, vn1 = sv1, vn2 = sv2;
#pragma unroll
    for (int k = 0; k < CC; k++) {
        float wl = sWls[k*CC + lane], wlv = sWlv[k*CC + lane];
        sn  += xs[k]     * wl;
        vn0 += xv[k*3+0] * wlv;
        vn1 += xv[k*3+1] * wlv;
        vn2 += xv[k*3+2] * wlv;
    }
    g_sv[n*CC + lane] = make_float4(sn, vn0, vn1, vn2);
    out[n*(LL*CC) + l*CC + lane] = sn;

    if (FUSE) {
        __syncwarp();
        ys[lane]       = sn;
        yv[lane*3 + 0] = vn0;
        yv[lane*3 + 1] = vn1;
        yv[lane*3 + 2] = vn2;
        __syncwarp();
        float a = 0.f, u0 = 0.f, u1 = 0.f, u2 = 0.f;
#pragma unroll
        for (int k = 0; k < CC; k++) {
            float ws = sWus[k*CC + lane], wv = sWuv[k*CC + lane];
            a  += ys[k]     * ws;
            u0 += yv[k*3+0] * wv;
            u1 += yv[k*3+1] * wv;
            u2 += yv[k*3+2] * wv;
        }
        g_up [n*CC + lane] = make_float4(a, u0, u1, u2);
        g_acc[n*CC + lane] = make_float4(0.f, 0.f, 0.f, 0.f);
    }
}

// ---------------- launch ------------------------------------------------------
extern "C" void kernel_launch(void* const* d_in, const int* in_sizes, int n_in,
                              void* d_out, int out_size) {
    const float* pos     = (const float*)d_in[0];
    const float* attrs   = (const float*)d_in[1];
    const float* shifts  = (const float*)d_in[2];
    const float* W_embed = (const float*)d_in[3];
    const float* W_up_s  = (const float*)d_in[4];
    const float* W_up_v  = (const float*)d_in[5];
    const float* R1      = (const float*)d_in[6];
    const float* R2      = (const float*)d_in[7];
    const float* R3      = (const float*)d_in[8];
    const float* W_out_s = (const float*)d_in[9];
    const float* W_out_v = (const float*)d_in[10];
    const float* Wsc_s   = (const float*)d_in[11];
    const float* Wsc_v   = (const float*)d_in[12];
    const float* Wp      = (const float*)d_in[13];
    const float* W_lin_s = (const float*)d_in[14];
    const float* W_lin_v = (const float*)d_in[15];
    const int*   ei      = (const int*)d_in[16];
    const int* src = ei;
    const int* dst = ei + EE;
    float* out = (float*)d_out;

    int smemT = (NB*HH + HH*HH + HH*5*CC) * (int)sizeof(float);   // 59392 B
    cudaFuncSetAttribute(k_table, cudaFuncAttributeMaxDynamicSharedMemorySize, smemT);

    k_pre0 <<<(TT + 255)/256, 256>>>(W_embed, W_up_s);           // su0 + zero bins
    k_init0<<<(NN*CC + 255)/256, 256>>>(attrs, W_embed);         // z + s/v/up/acc
    k_geom <<<(EE + 255)/256, 256>>>(pos, shifts, src, dst);     // Y1/tc/hist
    k_table<<<2*(TT/8), 256, smemT>>>(R1, R2, R3);               // both layers
    k_scan <<<1, 1024>>>();
    k_scatter<<<(EE + 255)/256, 256>>>();                        // compact (sorted)

    // layer 0 (v == 0 → 2-path, ss from species table, sorted edges)
    k_edge2<2><<<EBLK, 256>>>(0);
    k_nodeupd<true><<<(NN + NWB - 1)/NWB, NWB*32>>>(
        W_out_s, W_out_v, Wsc_s, Wsc_v, Wp, W_lin_s, W_lin_v,
        W_up_s + CC*CC, W_up_v + CC*CC, out, 0);

    // layer 1 (full 5-path)
    k_edge2<5><<<EBLK, 256>>>(1);
    k_nodeupd<false><<<(NN + NWB - 1)/NWB, NWB*32>>>(
        W_out_s + CC*CC, W_out_v + CC*CC,
        Wsc_s + ZZ*CC*CC, Wsc_v + ZZ*CC*CC, Wp + ZZ*5*CC,
        W_lin_s + CC*CC, W_lin_v + CC*CC,
        W_up_s, W_up_v, out, 1);
}